// round 1
// baseline (speedup 1.0000x reference)
#include <cuda_runtime.h>
#include <cuda_bf16.h>

// Problem-fixed geometry (KANLayer_60464549593380):
//   x:       [B=32768, D=256]  f32
//   coeffs:  [N=256,   F=2304] f32   (F = D * (DEGREE+1), DEGREE=8)
//   hweights:[N=256]           f32
//   out:     [B]               f32
//
// Algebraic collapse: out[b] = sum_f X[b,f] * w[f],  w = hweights @ coeffs.
// X[b, d*9+k] = T_k(tanh(x[b,d])) via Chebyshev recurrence.

#define DEG   8
#define NF    (DEG + 1)        // 9 features per dim
#define DDIM  256
#define FDIM  (DDIM * NF)      // 2304
#define NCHUNK 16

__device__ float g_w[FDIM];
__device__ float g_partial[NCHUNK][FDIM];

// Stage 1: partial column sums of hweights[n] * coeffs[n, f] over n-chunks.
// grid = (FDIM/256, NCHUNK), block = 256. Fully coalesced over f.
__global__ void k_reduce1(const float* __restrict__ coeffs,
                          const float* __restrict__ hw, int N) {
    const int f  = blockIdx.x * blockDim.x + threadIdx.x;
    const int c  = blockIdx.y;
    const int per = (N + NCHUNK - 1) / NCHUNK;   // 16 for N=256
    const int n0 = c * per;
    float s = 0.f;
    #pragma unroll 16
    for (int j = 0; j < per; ++j) {
        int n = n0 + j;
        if (n < N)
            s += hw[n] * coeffs[(size_t)n * FDIM + f];
    }
    g_partial[c][f] = s;
}

// Stage 2: combine partials into g_w.
__global__ void k_reduce2() {
    const int f = blockIdx.x * blockDim.x + threadIdx.x;
    if (f < FDIM) {
        float s = 0.f;
        #pragma unroll
        for (int c = 0; c < NCHUNK; ++c) s += g_partial[c][f];
        g_w[f] = s;
    }
}

// Accurate, flag-independent tanh: EX2-based, numerically stable, no overflow.
__device__ __forceinline__ float tanh_accurate(float x) {
    float a = fabsf(x);
    float e = __expf(-2.0f * a);          // MUFU.EX2 path, rel err ~2^-22
    float t = (1.0f - e) / (1.0f + e);    // in [0,1), stable (no cancellation)
    return copysignf(t, x);
}

// Main: persistent warps. Each warp keeps its 72 w-values (8 dims x 9 coeffs
// per lane) in registers and grid-strides over rows. Per row: 8 coalesced x
// loads per lane, tanh + Chebyshev recurrence + dot, butterfly reduce.
__global__ void __launch_bounds__(256)
k_main(const float* __restrict__ x, float* __restrict__ out, int B) {
    const int lane = threadIdx.x & 31;
    const int gw   = (blockIdx.x * blockDim.x + threadIdx.x) >> 5;
    const int nw   = (gridDim.x * blockDim.x) >> 5;

    // Load this lane's weights once (8 dims: d = lane + 32*i).
    float wr[8][NF];
    #pragma unroll
    for (int i = 0; i < 8; ++i) {
        #pragma unroll
        for (int k = 0; k < NF; ++k)
            wr[i][k] = g_w[(lane + 32 * i) * NF + k];
    }
    // T_0 == 1 contribution is row-independent: fold into the accumulator base.
    float base = 0.f;
    #pragma unroll
    for (int i = 0; i < 8; ++i) base += wr[i][0];

    for (int b = gw; b < B; b += nw) {
        const float* xr = x + (size_t)b * DDIM;
        float acc = base;
        #pragma unroll
        for (int i = 0; i < 8; ++i) {
            float xv = xr[lane + 32 * i];
            float t  = tanh_accurate(xv);
            acc = fmaf(wr[i][1], t, acc);
            float t2 = t + t;
            float Tp = 1.f, Tc = t;
            #pragma unroll
            for (int k = 2; k <= DEG; ++k) {
                float Tn = fmaf(t2, Tc, -Tp);   // T_{k} = 2t*T_{k-1} - T_{k-2}
                acc = fmaf(wr[i][k], Tn, acc);
                Tp = Tc; Tc = Tn;
            }
        }
        // Warp reduction.
        #pragma unroll
        for (int o = 16; o; o >>= 1)
            acc += __shfl_xor_sync(0xffffffffu, acc, o);
        if (lane == 0) out[b] = acc;
    }
}

extern "C" void kernel_launch(void* const* d_in, const int* in_sizes, int n_in,
                              void* d_out, int out_size) {
    const float* x      = (const float*)d_in[0];
    const float* coeffs = (const float*)d_in[1];
    const float* hw     = (const float*)d_in[2];
    float* out = (float*)d_out;

    const int B = out_size;        // 32768
    const int N = in_sizes[2];     // 256

    dim3 g1(FDIM / 256, NCHUNK);
    k_reduce1<<<g1, 256>>>(coeffs, hw, N);
    k_reduce2<<<FDIM / 256, 256>>>();

    // 296 blocks x 8 warps = 2368 persistent warps (~2/SM at ~90 regs/thread).
    k_main<<<296, 256>>>(x, out, B);
}

// round 2
// speedup vs baseline: 1.6208x; 1.6208x over previous
#include <cuda_runtime.h>
#include <cuda_bf16.h>

// KANLayer_60464549593380 on GB300:
//   x:[B=32768, D=256] f32, coeffs:[N=256, F=2304] f32, hweights:[N=256] f32
//   out[b] = sum_f X[b,f] * w[f],   w = hweights @ coeffs   (summation reorder)
//   X[b, d*9+k] = T_k(tanh(x[b,d]))
// Further fold: per dim, sum_k w_k T_k(t) is a degree-8 polynomial; convert
// Chebyshev->monomial once, evaluate with packed-f32x2 Horner (8 FFMA2 / 2 dims).

#define DEG    8
#define NF     (DEG + 1)      // 9
#define DDIM   256
#define FDIM   (DDIM * NF)    // 2304
#define F4DIM  (FDIM / 4)     // 576
#define NCHUNK 16

__device__ float g_partial[NCHUNK][FDIM];
// Packed monomial coeffs: [lane 0..31][chain 0..3][deg j 0..8] as f32x2
// (.x = dim 8*lane+chain, .y = dim 8*lane+chain+4)
__device__ unsigned long long g_apk[32 * 4 * NF];

// ---------------- f32x2 helpers (sm_103a packed math) ----------------
__device__ __forceinline__ unsigned long long fma2(unsigned long long a,
                                                   unsigned long long b,
                                                   unsigned long long c) {
    unsigned long long d;
    asm("fma.rn.f32x2 %0, %1, %2, %3;" : "=l"(d) : "l"(a), "l"(b), "l"(c));
    return d;
}
__device__ __forceinline__ unsigned long long add2(unsigned long long a,
                                                   unsigned long long b) {
    unsigned long long d;
    asm("add.rn.f32x2 %0, %1, %2;" : "=l"(d) : "l"(a), "l"(b));
    return d;
}
__device__ __forceinline__ unsigned long long pack2(float lo, float hi) {
    unsigned long long d;
    asm("mov.b64 %0, {%1, %2};" : "=l"(d) : "f"(lo), "f"(hi));
    return d;
}
__device__ __forceinline__ float unpack_sum(unsigned long long v) {
    float lo, hi;
    asm("mov.b64 {%0, %1}, %2;" : "=f"(lo), "=f"(hi) : "l"(v));
    return lo + hi;
}

// ---------------- Stage 1: partial w[f] = sum_n hw[n]*coeffs[n,f] ----------------
// 9216 threads (36 blocks x 256): thread -> (f4 column, n-chunk). float4 loads,
// 16-deep MLP, fully coalesced. 2.4MB total -> ~1us.
__global__ void k_wsum(const float4* __restrict__ c4,
                       const float* __restrict__ hw, int N) {
    const int idx = blockIdx.x * blockDim.x + threadIdx.x;   // 0..9215
    const int f4  = idx % F4DIM;
    const int ch  = idx / F4DIM;
    const int per = (N + NCHUNK - 1) / NCHUNK;               // 16
    const int n0  = ch * per;
    float4 s = make_float4(0.f, 0.f, 0.f, 0.f);
    #pragma unroll 16
    for (int j = 0; j < per; ++j) {
        int n = n0 + j;
        if (n < N) {
            float  h = hw[n];
            float4 v = c4[(size_t)n * F4DIM + f4];
            s.x = fmaf(h, v.x, s.x);
            s.y = fmaf(h, v.y, s.y);
            s.z = fmaf(h, v.z, s.z);
            s.w = fmaf(h, v.w, s.w);
        }
    }
    ((float4*)g_partial[ch])[f4] = s;
}

// ---------------- Stage 2: combine + Chebyshev->monomial + pack ----------------
// One block, 256 threads, one thread per dim.
__global__ void k_wfin() {
    const int d = threadIdx.x;                // dim 0..255
    float w[NF];
    #pragma unroll
    for (int k = 0; k < NF; ++k) {
        float s = 0.f;
        #pragma unroll
        for (int c = 0; c < NCHUNK; ++c) s += g_partial[c][d * NF + k];
        w[k] = s;
    }
    float a[NF];
    a[0] = w[0] - w[2] + w[4] - w[6] + w[8];
    a[1] = w[1] - 3.f * w[3] + 5.f * w[5] - 7.f * w[7];
    a[2] = 2.f * w[2] - 8.f * w[4] + 18.f * w[6] - 32.f * w[8];
    a[3] = 4.f * w[3] - 20.f * w[5] + 56.f * w[7];
    a[4] = 8.f * w[4] - 48.f * w[6] + 160.f * w[8];
    a[5] = 16.f * w[5] - 112.f * w[7];
    a[6] = 32.f * w[6] - 256.f * w[8];
    a[7] = 64.f * w[7];
    a[8] = 128.f * w[8];

    const int lane = d >> 3, q = d & 7;
    const int p = q & 3, half = q >> 2;       // chain, lo/hi slot
    float* gf = (float*)g_apk;
    #pragma unroll
    for (int j = 0; j < NF; ++j)
        gf[(((lane * 4 + p) * NF) + j) * 2 + half] = a[j];
}

// ---------------- Main: warp-per-row, persistent, packed Horner ----------------
__global__ void __launch_bounds__(256, 2)
k_main(const float* __restrict__ x, float* __restrict__ out, int B) {
    const int lane = threadIdx.x & 31;
    const int gw   = (blockIdx.x * blockDim.x + threadIdx.x) >> 5;
    const int nw   = (gridDim.x * blockDim.x) >> 5;

    // Lane owns dims 8*lane .. 8*lane+7. Load 36 packed coeffs once.
    unsigned long long c[4][NF];
    {
        const unsigned long long* ap = g_apk + lane * 4 * NF;
        #pragma unroll
        for (int p = 0; p < 4; ++p)
            #pragma unroll
            for (int j = 0; j < NF; ++j)
                c[p][j] = ap[p * NF + j];
    }

    for (int b = gw; b < B; b += nw) {
        const float4* xr = (const float4*)(x + (size_t)b * DDIM) + lane * 2;
        float4 xa = xr[0];                    // dims 8l..8l+3
        float4 xb = xr[1];                    // dims 8l+4..8l+7
        float xv[8] = {xa.x, xa.y, xa.z, xa.w, xb.x, xb.y, xb.z, xb.w};

        float t[8];
        #pragma unroll
        for (int q = 0; q < 8; ++q) {
            float aab = fabsf(xv[q]);
            float e   = __expf(-2.0f * aab);              // FMUL + MUFU.EX2
            float tv  = __fdividef(1.0f - e, 1.0f + e);   // MUFU.RCP + FMUL
            t[q] = copysignf(tv, xv[q]);
        }

        unsigned long long tp[4], h[4];
        #pragma unroll
        for (int p = 0; p < 4; ++p) {
            tp[p] = pack2(t[p], t[p + 4]);
            h[p]  = c[p][DEG];
        }
        #pragma unroll
        for (int j = DEG - 1; j >= 0; --j)
            #pragma unroll
            for (int p = 0; p < 4; ++p)
                h[p] = fma2(tp[p], h[p], c[p][j]);        // Horner, 4 ILP chains

        float acc = unpack_sum(add2(add2(h[0], h[1]), add2(h[2], h[3])));

        #pragma unroll
        for (int o = 16; o; o >>= 1)
            acc += __shfl_xor_sync(0xffffffffu, acc, o);
        if (lane == 0) out[b] = acc;
    }
}

extern "C" void kernel_launch(void* const* d_in, const int* in_sizes, int n_in,
                              void* d_out, int out_size) {
    const float* x      = (const float*)d_in[0];
    const float* coeffs = (const float*)d_in[1];
    const float* hw     = (const float*)d_in[2];
    float* out = (float*)d_out;

    const int B = out_size;       // 32768
    const int N = in_sizes[2];    // 256

    k_wsum<<<(F4DIM * NCHUNK) / 256, 256>>>((const float4*)coeffs, hw, N);
    k_wfin<<<1, 256>>>();
    k_main<<<296, 256>>>(x, out, B);
}

// round 3
// speedup vs baseline: 1.7817x; 1.0992x over previous
#include <cuda_runtime.h>
#include <cuda_bf16.h>

// KANLayer_60464549593380 on GB300 (sm_103a):
//   x:[B=32768, D=256] f32, coeffs:[N=256, F=2304] f32, hweights:[N=256] f32
//   out[b] = sum_f X[b,f] * w[f],   w = hweights @ coeffs   (summation reorder)
//   Per dim, sum_k w_k T_k(tanh(x)) is a degree-8 polynomial; convert
//   Chebyshev->monomial (in k_main prologue), evaluate with packed f32x2
//   Horner. x streamed via cp.async double-buffer to stay DRAM-bound.

#define DEG    8
#define NF     (DEG + 1)      // 9
#define DDIM   256
#define FDIM   (DDIM * NF)    // 2304
#define F4DIM  (FDIM / 4)     // 576

__device__ float g_w[FDIM];

// ---------------- f32x2 helpers ----------------
__device__ __forceinline__ unsigned long long fma2(unsigned long long a,
                                                   unsigned long long b,
                                                   unsigned long long c) {
    unsigned long long d;
    asm("fma.rn.f32x2 %0, %1, %2, %3;" : "=l"(d) : "l"(a), "l"(b), "l"(c));
    return d;
}
__device__ __forceinline__ unsigned long long add2(unsigned long long a,
                                                   unsigned long long b) {
    unsigned long long d;
    asm("add.rn.f32x2 %0, %1, %2;" : "=l"(d) : "l"(a), "l"(b));
    return d;
}
__device__ __forceinline__ unsigned long long pack2(float lo, float hi) {
    unsigned long long d;
    asm("mov.b64 %0, {%1, %2};" : "=l"(d) : "f"(lo), "f"(hi));
    return d;
}
__device__ __forceinline__ float unpack_sum(unsigned long long v) {
    float lo, hi;
    asm("mov.b64 {%0, %1}, %2;" : "=f"(lo), "=f"(hi) : "l"(v));
    return lo + hi;
}

// ---------------- cp.async helpers ----------------
__device__ __forceinline__ void cpa16(void* dst_smem, const void* src) {
    unsigned s = (unsigned)__cvta_generic_to_shared(dst_smem);
    asm volatile("cp.async.cg.shared.global [%0], [%1], 16;" :: "r"(s), "l"(src));
}
__device__ __forceinline__ void cpa_commit() {
    asm volatile("cp.async.commit_group;");
}
__device__ __forceinline__ void cpa_wait1() {
    asm volatile("cp.async.wait_group 1;");
}

// ---------------- Single prep kernel: w[f] = sum_n hw[n]*coeffs[n,f] --------
// 72 blocks x 256. Block owns 8 f4-columns (32 f). Thread (f4l, grp):
// 8 float4 loads over its n-slice, smem reduce over 32 groups.
__global__ void k_wprep(const float4* __restrict__ c4,
                        const float* __restrict__ hw, int N) {
    __shared__ float4 red[32][8];
    const int f4l = threadIdx.x & 7;
    const int grp = threadIdx.x >> 3;              // 0..31
    const int f4  = blockIdx.x * 8 + f4l;
    float4 s = make_float4(0.f, 0.f, 0.f, 0.f);
    #pragma unroll 8
    for (int j = 0; j < 8; ++j) {
        int n = grp * 8 + j;
        if (n < N) {
            float  h = hw[n];
            float4 v = c4[(size_t)n * F4DIM + f4];
            s.x = fmaf(h, v.x, s.x);
            s.y = fmaf(h, v.y, s.y);
            s.z = fmaf(h, v.z, s.z);
            s.w = fmaf(h, v.w, s.w);
        }
    }
    red[grp][f4l] = s;
    __syncthreads();
    if (threadIdx.x < 8) {
        float4 acc = red[0][threadIdx.x];
        #pragma unroll
        for (int g = 1; g < 32; ++g) {
            float4 v = red[g][threadIdx.x];
            acc.x += v.x; acc.y += v.y; acc.z += v.z; acc.w += v.w;
        }
        ((float4*)g_w)[blockIdx.x * 8 + threadIdx.x] = acc;
    }
}

// Chebyshev->monomial for one dim's 9 weights.
__device__ __forceinline__ void cheb2mono(const float* __restrict__ w, float* a) {
    a[0] = w[0] - w[2] + w[4] - w[6] + w[8];
    a[1] = w[1] - 3.f * w[3] + 5.f * w[5] - 7.f * w[7];
    a[2] = 2.f * w[2] - 8.f * w[4] + 18.f * w[6] - 32.f * w[8];
    a[3] = 4.f * w[3] - 20.f * w[5] + 56.f * w[7];
    a[4] = 8.f * w[4] - 48.f * w[6] + 160.f * w[8];
    a[5] = 16.f * w[5] - 112.f * w[7];
    a[6] = 32.f * w[6] - 256.f * w[8];
    a[7] = 64.f * w[7];
    a[8] = 128.f * w[8];
}

// ---------------- Main ----------------
// Warp-per-2-rows, persistent grid-stride, cp.async double-buffered x tiles.
// Lane owns dims 8l..8l+7; 4 packed Horner chains pairing dims (8l+p, 8l+p+4).
__global__ void __launch_bounds__(256, 2)
k_main(const float* __restrict__ x, float* __restrict__ out, int B) {
    __shared__ float4 smx[8][2][2][64];   // [warp][buf][row][64 float4] = 32KB
    const int lane = threadIdx.x & 31;
    const int wib  = threadIdx.x >> 5;
    const int gw   = (blockIdx.x * blockDim.x + threadIdx.x) >> 5;
    const int nw   = (gridDim.x * blockDim.x) >> 5;

    // Prologue: load w for this lane's 8 dims, convert to packed monomials.
    unsigned long long c[4][NF];
    {
        #pragma unroll
        for (int p = 0; p < 4; ++p) {
            float alo[NF], ahi[NF], wlo[NF], whi[NF];
            const float* wl = g_w + (8 * lane + p) * NF;
            const float* wh = g_w + (8 * lane + p + 4) * NF;
            #pragma unroll
            for (int k = 0; k < NF; ++k) { wlo[k] = wl[k]; whi[k] = wh[k]; }
            cheb2mono(wlo, alo);
            cheb2mono(whi, ahi);
            #pragma unroll
            for (int j = 0; j < NF; ++j) c[p][j] = pack2(alo[j], ahi[j]);
        }
    }

    const float4* x4 = (const float4*)x;
    const int stride = 2 * nw;
    const int b0 = 2 * gw;

    // Prefetch first pair into buf 0.
    {
        if (b0 < B) {
            const float4* r0 = x4 + (size_t)b0 * 64;
            cpa16(&smx[wib][0][0][lane],      r0 + lane);
            cpa16(&smx[wib][0][0][lane + 32], r0 + lane + 32);
            if (b0 + 1 < B) {
                cpa16(&smx[wib][0][1][lane],      r0 + 64 + lane);
                cpa16(&smx[wib][0][1][lane + 32], r0 + 64 + lane + 32);
            }
        }
        cpa_commit();
    }

    int pb = 0;
    for (int b = b0; b < B; b += stride) {
        // Prefetch next pair into the other buffer.
        {
            int bn = b + stride;
            if (bn < B) {
                const float4* r0 = x4 + (size_t)bn * 64;
                cpa16(&smx[wib][pb ^ 1][0][lane],      r0 + lane);
                cpa16(&smx[wib][pb ^ 1][0][lane + 32], r0 + lane + 32);
                if (bn + 1 < B) {
                    cpa16(&smx[wib][pb ^ 1][1][lane],      r0 + 64 + lane);
                    cpa16(&smx[wib][pb ^ 1][1][lane + 32], r0 + 64 + lane + 32);
                }
            }
            cpa_commit();
        }
        cpa_wait1();       // current buffer's group done
        __syncwarp();

        const int nrow = (b + 1 < B) ? 2 : 1;
        #pragma unroll
        for (int r = 0; r < 2; ++r) {
            if (r >= nrow) break;
            float4 xa = smx[wib][pb][r][2 * lane];
            float4 xb = smx[wib][pb][r][2 * lane + 1];
            float xv[8] = {xa.x, xa.y, xa.z, xa.w, xb.x, xb.y, xb.z, xb.w};

            float t[8];
            #pragma unroll
            for (int q = 0; q < 8; ++q) {
                // tanh(x) = sign(x)*(1-e)/(1+e), e = 2^(-2*log2(e)*|x|)
                float e  = exp2f(fabsf(xv[q]) * -2.885390081777927f);
                float tv = __fdividef(1.0f - e, 1.0f + e);
                t[q] = copysignf(tv, xv[q]);
            }

            unsigned long long tp[4], h[4];
            #pragma unroll
            for (int p = 0; p < 4; ++p) {
                tp[p] = pack2(t[p], t[p + 4]);
                h[p]  = c[p][DEG];
            }
            #pragma unroll
            for (int j = DEG - 1; j >= 0; --j)
                #pragma unroll
                for (int p = 0; p < 4; ++p)
                    h[p] = fma2(tp[p], h[p], c[p][j]);

            float acc = unpack_sum(add2(add2(h[0], h[1]), add2(h[2], h[3])));
            #pragma unroll
            for (int o = 16; o; o >>= 1)
                acc += __shfl_xor_sync(0xffffffffu, acc, o);
            if (lane == 0) out[b + r] = acc;
        }
        pb ^= 1;
    }
}

extern "C" void kernel_launch(void* const* d_in, const int* in_sizes, int n_in,
                              void* d_out, int out_size) {
    const float* x      = (const float*)d_in[0];
    const float* coeffs = (const float*)d_in[1];
    const float* hw     = (const float*)d_in[2];
    float* out = (float*)d_out;

    const int B = out_size;       // 32768
    const int N = in_sizes[2];    // 256

    k_wprep<<<F4DIM / 8, 256>>>((const float4*)coeffs, hw, N);
    k_main<<<296, 256>>>(x, out, B);
}

// round 4
// speedup vs baseline: 1.9746x; 1.1083x over previous
#include <cuda_runtime.h>

// KANLayer_60464549593380 on GB300 (sm_103a):
//   out[b] = sum_d P_d(tanh(x[b,d])),  P_d = degree-8 monomial poly from
//   w = hweights @ coeffs (Chebyshev basis folded: summation reorder + basis
//   change). Thread-per-quarter-row, coeffs broadcast from smem, packed f32x2
//   Horner, cp.async double-buffered x staging.

#define DEG   8
#define NF    9
#define DDIM  256
#define FDIM  2304
#define F4DIM 576
#define ROWS  32            // rows per block
#define XPAD  36            // floats per row in stage buffer (bank-conflict-free)

__device__ float g_w[FDIM];

// ---------------- packed f32x2 / MUFU / cp.async helpers ----------------
__device__ __forceinline__ unsigned long long fma2(unsigned long long a,
                                                   unsigned long long b,
                                                   unsigned long long c) {
    unsigned long long d;
    asm("fma.rn.f32x2 %0, %1, %2, %3;" : "=l"(d) : "l"(a), "l"(b), "l"(c));
    return d;
}
__device__ __forceinline__ unsigned long long add2(unsigned long long a,
                                                   unsigned long long b) {
    unsigned long long d;
    asm("add.rn.f32x2 %0, %1, %2;" : "=l"(d) : "l"(a), "l"(b));
    return d;
}
__device__ __forceinline__ unsigned long long pack2(float lo, float hi) {
    unsigned long long d;
    asm("mov.b64 %0, {%1, %2};" : "=l"(d) : "f"(lo), "f"(hi));
    return d;
}
__device__ __forceinline__ float unpack_sum(unsigned long long v) {
    float lo, hi;
    asm("mov.b64 {%0, %1}, %2;" : "=f"(lo), "=f"(hi) : "l"(v));
    return lo + hi;
}
__device__ __forceinline__ float ex2a(float v) {
    float r; asm("ex2.approx.ftz.f32 %0, %1;" : "=f"(r) : "f"(v)); return r;
}
__device__ __forceinline__ float rcpa(float v) {
    float r; asm("rcp.approx.ftz.f32 %0, %1;" : "=f"(r) : "f"(v)); return r;
}
__device__ __forceinline__ float tanh_fast(float v) {
    float e = ex2a(v * -2.885390081777927f);   // exp(-2v)
    return (1.0f - e) * rcpa(1.0f + e);        // (1-e)/(1+e); |v|<~40 always
}
__device__ __forceinline__ void cpa16(void* dst_smem, const void* src) {
    unsigned s = (unsigned)__cvta_generic_to_shared(dst_smem);
    asm volatile("cp.async.cg.shared.global [%0], [%1], 16;" :: "r"(s), "l"(src));
}
__device__ __forceinline__ void cpa_commit() { asm volatile("cp.async.commit_group;"); }
__device__ __forceinline__ void cpa_wait1()  { asm volatile("cp.async.wait_group 1;"); }

// ---------------- Prep: w[f] = sum_n hw[n]*coeffs[n,f] ----------------
// 576 blocks (one per float4 column) x 128 threads; tree reduce in smem.
__global__ void k_wprep(const float4* __restrict__ c4,
                        const float* __restrict__ hw, int N) {
    __shared__ float4 red[128];
    const int col = blockIdx.x;
    const int t   = threadIdx.x;
    float4 s = make_float4(0.f, 0.f, 0.f, 0.f);
    for (int n = t; n < N; n += 128) {
        float  h = hw[n];
        float4 v = c4[(size_t)n * F4DIM + col];
        s.x = fmaf(h, v.x, s.x);
        s.y = fmaf(h, v.y, s.y);
        s.z = fmaf(h, v.z, s.z);
        s.w = fmaf(h, v.w, s.w);
    }
    red[t] = s;
    __syncthreads();
    #pragma unroll
    for (int o = 64; o >= 1; o >>= 1) {
        if (t < o) {
            float4 b = red[t + o];
            red[t].x += b.x; red[t].y += b.y; red[t].z += b.z; red[t].w += b.w;
        }
        __syncthreads();
    }
    if (t == 0) ((float4*)g_w)[col] = red[0];
}

// Chebyshev -> monomial for one dim's 9 weights.
__device__ __forceinline__ void cheb2mono(const float* __restrict__ w, float* a) {
    a[0] = w[0] - w[2] + w[4] - w[6] + w[8];
    a[1] = w[1] - 3.f * w[3] + 5.f * w[5] - 7.f * w[7];
    a[2] = 2.f * w[2] - 8.f * w[4] + 18.f * w[6] - 32.f * w[8];
    a[3] = 4.f * w[3] - 20.f * w[5] + 56.f * w[7];
    a[4] = 8.f * w[4] - 48.f * w[6] + 160.f * w[8];
    a[5] = 16.f * w[5] - 112.f * w[7];
    a[6] = 32.f * w[6] - 256.f * w[8];
    a[7] = 64.f * w[7];
    a[8] = 128.f * w[8];
}

// ---------------- Main ----------------
// Block: 128 threads, 32 rows. Thread (rloc, q) owns row rloc, dim groups
// [32c + 8q, +8) per chunk c (q in 0..3). Combine across q via 2 shfl_xor.
__global__ void __launch_bounds__(128)
k_main(const float* __restrict__ x, float* __restrict__ out, int B) {
    __shared__ float xs[2][ROWS][XPAD];                 // 9216 B
    __shared__ unsigned long long cs[NF][DDIM / 2];     // 9216 B, coeff-major
    const int t    = threadIdx.x;
    const int lane = t & 31;
    const int q    = lane & 3;
    const int rloc = (t >> 5) * 8 + (lane >> 2);        // 0..31
    const int row0 = blockIdx.x * ROWS;
    const float4* xg = (const float4*)x + (size_t)row0 * 64;  // 64 f4 per row

    // Kick off chunk 0 staging immediately.
    {
        #pragma unroll
        for (int k = 0; k < 2; ++k) {
            int idx = t + 128 * k;               // 0..255 f4 slots
            int r = idx >> 3, s = idx & 7;
            cpa16(&xs[0][r][s * 4], xg + (size_t)r * 64 + s);
        }
        cpa_commit();
    }

    // Build packed monomial table while chunk 0 is in flight.
    // Thread p builds dim pair (2p, 2p+1); cs[j][p] = (a_{2p}[j], a_{2p+1}[j]).
    {
        const int p = t;
        float wl[NF], wh[NF], al[NF], ah[NF];
        #pragma unroll
        for (int k = 0; k < NF; ++k) {
            wl[k] = g_w[(2 * p) * NF + k];
            wh[k] = g_w[(2 * p + 1) * NF + k];
        }
        cheb2mono(wl, al);
        cheb2mono(wh, ah);
        #pragma unroll
        for (int j = 0; j < NF; ++j) cs[j][p] = pack2(al[j], ah[j]);
    }

    unsigned long long accA = pack2(0.f, 0.f);
    unsigned long long accB = pack2(0.f, 0.f);

    #pragma unroll
    for (int c = 0; c < 8; ++c) {
        const int buf = c & 1;
        __syncthreads();                         // buf^1 free; coeffs ready (c=0)
        if (c < 7) {
            const float4* xn = xg + (c + 1) * 8;
            #pragma unroll
            for (int k = 0; k < 2; ++k) {
                int idx = t + 128 * k;
                int r = idx >> 3, s = idx & 7;
                cpa16(&xs[buf ^ 1][r][s * 4], xn + (size_t)r * 64 + s);
            }
        }
        cpa_commit();
        cpa_wait1();                             // chunk c landed
        __syncthreads();                         // visible block-wide

        const float* xr = xs[buf][rloc] + 8 * q;
        float4 xa = *(const float4*)(xr);
        float4 xb = *(const float4*)(xr + 4);
        float tv[8];
        tv[0] = tanh_fast(xa.x); tv[1] = tanh_fast(xa.y);
        tv[2] = tanh_fast(xa.z); tv[3] = tanh_fast(xa.w);
        tv[4] = tanh_fast(xb.x); tv[5] = tanh_fast(xb.y);
        tv[6] = tanh_fast(xb.z); tv[7] = tanh_fast(xb.w);

        const int P0 = c * 16 + q * 4;
        #pragma unroll
        for (int i = 0; i < 4; ++i) {
            unsigned long long tp = pack2(tv[2 * i], tv[2 * i + 1]);
            unsigned long long h  = cs[DEG][P0 + i];
            #pragma unroll
            for (int j = DEG - 1; j >= 0; --j)
                h = fma2(tp, h, cs[j][P0 + i]);
            if (i & 1) accB = add2(accB, h);
            else       accA = add2(accA, h);
        }
    }

    float a = unpack_sum(add2(accA, accB));
    a += __shfl_xor_sync(0xffffffffu, a, 1);
    a += __shfl_xor_sync(0xffffffffu, a, 2);
    if (q == 0) {
        int row = row0 + rloc;
        if (row < B) out[row] = a;
    }
}

extern "C" void kernel_launch(void* const* d_in, const int* in_sizes, int n_in,
                              void* d_out, int out_size) {
    const float* x      = (const float*)d_in[0];
    const float* coeffs = (const float*)d_in[1];
    const float* hw     = (const float*)d_in[2];
    float* out = (float*)d_out;

    const int B = out_size;       // 32768 (multiple of ROWS)
    const int N = in_sizes[2];    // 256

    k_wprep<<<F4DIM, 128>>>((const float4*)coeffs, hw, N);
    k_main<<<B / ROWS, 128>>>(x, out, B);
}